// round 12
// baseline (speedup 1.0000x reference)
#include <cuda_runtime.h>

// LSTM autoencoder, fully fused. B=4096, T=512, F=8, H=16.
// R7: ONE element per FULL warp (32 lanes). Lane l owns gate rows l and 32+l
// (gate order i,f,g,o). 4096 warps -> occupancy doubles (grid was the cap);
// per-warp critical work halves. Pure fp32, shuffles only, zero smem.

#define B_ 4096
#define T_ 512
#define F_ 8
#define H_ 16

typedef unsigned long long u64;

__device__ __forceinline__ u64 pk2(float lo, float hi) {
    u64 r; asm("mov.b64 %0,{%1,%2};" : "=l"(r) : "f"(lo), "f"(hi)); return r;
}
__device__ __forceinline__ void fma2(u64& d, u64 a, u64 b) {
    asm("fma.rn.f32x2 %0,%1,%2,%0;" : "+l"(d) : "l"(a), "l"(b));
}
__device__ __forceinline__ float hadd2(u64 v) {
    float lo, hi; asm("mov.b64 {%0,%1},%2;" : "=f"(lo), "=f"(hi) : "l"(v));
    return lo + hi;
}
__device__ __forceinline__ float tanh_fast(float x) {
    float r; asm("tanh.approx.f32 %0,%1;" : "=f"(r) : "f"(x)); return r;
}
__device__ __forceinline__ void ldg2(u64& a, u64& b, const float* p) {
    asm("ld.global.nc.v2.u64 {%0,%1},[%2];" : "=l"(a), "=l"(b) : "l"(p));
}
__device__ __forceinline__ void prefetch_l1(const float* p) {
    float d; asm volatile("ld.global.nc.b32 %0,[%1];" : "=f"(d) : "l"(p));
}

__global__ __launch_bounds__(128, 7)
void lstm_ae_kernel(const float* __restrict__ x,
                    const float* __restrict__ eWih, const float* __restrict__ eWhh,
                    const float* __restrict__ ebih, const float* __restrict__ ebhh,
                    const float* __restrict__ dWih, const float* __restrict__ dWhh,
                    const float* __restrict__ dbih, const float* __restrict__ dbhh,
                    const float* __restrict__ oW,  const float* __restrict__ ob,
                    float* __restrict__ out)
{
    const int tid = blockIdx.x * blockDim.x + threadIdx.x;
    const int b   = tid >> 5;                 // warp = one batch element
    const int l   = tid & 31;                 // lane
    const unsigned FULL = 0xffffffffu;

    // lane l owns gate rows: r_lo = l (i for l<16, f for l>=16)
    //                        r_hi = 32+l (g for l<16, o for l>=16)
    const int r_lo = l;
    const int r_hi = 32 + l;
    // sigmoid rows pre-scaled by 0.5 (sigmoid(z)=0.5*tanh(0.5z)+0.5); g-rows not.
    const float s_hi = (l < 16) ? 1.0f : 0.5f;

    // ---------------- encoder weights (2 rows per lane, k-pairs) -----------
    u64 whl[8], whu[8];     // hidden->row_lo / row_hi
    u64 wil[4], wiu[4];     // input->row_lo / row_hi
    float bias_lo = 0.5f * (ebih[r_lo] + ebhh[r_lo]);
    float bias_hi = s_hi * (ebih[r_hi] + ebhh[r_hi]);
    #pragma unroll
    for (int j = 0; j < 8; ++j) {
        whl[j] = pk2(0.5f * eWhh[r_lo * H_ + 2 * j], 0.5f * eWhh[r_lo * H_ + 2 * j + 1]);
        whu[j] = pk2(s_hi * eWhh[r_hi * H_ + 2 * j], s_hi * eWhh[r_hi * H_ + 2 * j + 1]);
    }
    #pragma unroll
    for (int j = 0; j < 4; ++j) {
        wil[j] = pk2(0.5f * eWih[r_lo * F_ + 2 * j], 0.5f * eWih[r_lo * F_ + 2 * j + 1]);
        wiu[j] = pk2(s_hi * eWih[r_hi * F_ + 2 * j], s_hi * eWih[r_hi * F_ + 2 * j + 1]);
    }

    float h = 0.0f, c = 0.0f;
    const float* xr = x + (size_t)b * T_ * F_;
    prefetch_l1(xr);

    // ---------------- encoder recurrence ----------------
    for (int t = 0; t < T_; ++t) {
        int tp = (t + 4 < T_) ? (t + 4) : (T_ - 1);
        prefetch_l1(xr + tp * F_);

        u64 alo = pk2(bias_lo, 0.f);
        u64 ahi = pk2(bias_hi, 0.f);

        // input projection: broadcast load (all lanes same addr)
        u64 xq0, xq1, xq2, xq3;
        ldg2(xq0, xq1, xr + t * F_);
        ldg2(xq2, xq3, xr + t * F_ + 4);
        fma2(alo, xq0, wil[0]); fma2(ahi, xq0, wiu[0]);
        fma2(alo, xq1, wil[1]); fma2(ahi, xq1, wiu[1]);
        fma2(alo, xq2, wil[2]); fma2(ahi, xq2, wiu[2]);
        fma2(alo, xq3, wil[3]); fma2(ahi, xq3, wiu[3]);

        // recurrent projection: h lives on lanes 0-15
        #pragma unroll
        for (int k = 0; k < 8; ++k) {
            float hl = __shfl_sync(FULL, h, 2 * k);
            float hh = __shfl_sync(FULL, h, 2 * k + 1);
            u64 hp = pk2(hl, hh);
            fma2(alo, hp, whl[k]);
            fma2(ahi, hp, whu[k]);
        }

        // activations: lanes<16 own (i,g); lanes>=16 own (f,o)
        float t_lo = tanh_fast(hadd2(alo));
        float t_hi = tanh_fast(hadd2(ahi));
        float sa = __fmaf_rn(0.5f, t_lo, 0.5f);      // i (l<16) / f (l>=16)
        float sb = __fmaf_rn(0.5f, t_hi, 0.5f);      // o (l>=16)
        float fg = __shfl_down_sync(FULL, sa, 16);   // f_l  -> lanes < 16
        float og = __shfl_down_sync(FULL, sb, 16);   // o_l  -> lanes < 16
        c = __fmaf_rn(fg, c, sa * t_hi);             // i*g on l<16 (junk elsewhere)
        h = og * tanh_fast(c);                       // valid on lanes 0-15
    }

    // ---------------- decoder setup ----------------
    // Input is hT repeated -> per-batch constant projection.
    float xpg_lo = dbih[r_lo] + dbhh[r_lo];
    float xpg_hi = dbih[r_hi] + dbhh[r_hi];
    #pragma unroll
    for (int k = 0; k < H_; ++k) {
        float hk = __shfl_sync(FULL, h, k);
        xpg_lo += hk * __ldg(&dWih[r_lo * H_ + k]);
        xpg_hi += hk * __ldg(&dWih[r_hi * H_ + k]);
    }
    xpg_lo *= 0.5f;
    xpg_hi *= s_hi;
    #pragma unroll
    for (int j = 0; j < 8; ++j) {          // reuse weight registers
        whl[j] = pk2(0.5f * dWhh[r_lo * H_ + 2 * j], 0.5f * dWhh[r_lo * H_ + 2 * j + 1]);
        whu[j] = pk2(s_hi * dWhh[r_hi * H_ + 2 * j], s_hi * dWhh[r_hi * H_ + 2 * j + 1]);
    }
    // output head: lane computes feature l&7; lanes 0-7 store (reuse wil/wiu)
    const int fo = l & 7;
    #pragma unroll
    for (int j = 0; j < 4; ++j) {
        wil[j] = pk2(oW[fo * H_ + 2 * j],     oW[fo * H_ + 2 * j + 1]);
        wiu[j] = pk2(oW[fo * H_ + 8 + 2 * j], oW[fo * H_ + 8 + 2 * j + 1]);
    }
    const float obv = __ldg(&ob[fo]);

    h = 0.0f; c = 0.0f;
    float* outp = out + (size_t)b * T_ * F_;

    // ---------------- decoder recurrence + fused output head ----------------
    for (int t = 0; t < T_; ++t) {
        u64 alo = pk2(xpg_lo, 0.f);
        u64 ahi = pk2(xpg_hi, 0.f);
        u64 oa  = pk2(obv, 0.f);

        #pragma unroll
        for (int k = 0; k < 8; ++k) {
            float hl = __shfl_sync(FULL, h, 2 * k);      // h_{t-1}
            float hh = __shfl_sync(FULL, h, 2 * k + 1);
            u64 hp = pk2(hl, hh);
            fma2(alo, hp, whl[k]);
            fma2(ahi, hp, whu[k]);
            fma2(oa,  hp, (k < 4) ? wil[k] : wiu[k - 4]); // head on h_{t-1}
        }
        if (t > 0 && l < 8) outp[(t - 1) * F_ + l] = hadd2(oa);

        float t_lo = tanh_fast(hadd2(alo));
        float t_hi = tanh_fast(hadd2(ahi));
        float sa = __fmaf_rn(0.5f, t_lo, 0.5f);
        float sb = __fmaf_rn(0.5f, t_hi, 0.5f);
        float fg = __shfl_down_sync(FULL, sa, 16);
        float og = __shfl_down_sync(FULL, sb, 16);
        c = __fmaf_rn(fg, c, sa * t_hi);
        h = og * tanh_fast(c);
    }

    // epilogue: project decoded[T-1]
    {
        u64 oa = pk2(obv, 0.f);
        #pragma unroll
        for (int k = 0; k < 8; ++k) {
            float hl = __shfl_sync(FULL, h, 2 * k);
            float hh = __shfl_sync(FULL, h, 2 * k + 1);
            u64 hp = pk2(hl, hh);
            fma2(oa, hp, (k < 4) ? wil[k] : wiu[k - 4]);
        }
        if (l < 8) outp[(T_ - 1) * F_ + l] = hadd2(oa);
    }
}

extern "C" void kernel_launch(void* const* d_in, const int* in_sizes, int n_in,
                              void* d_out, int out_size)
{
    const float* x    = (const float*)d_in[0];
    const float* eWih = (const float*)d_in[1];
    const float* eWhh = (const float*)d_in[2];
    const float* ebih = (const float*)d_in[3];
    const float* ebhh = (const float*)d_in[4];
    const float* dWih = (const float*)d_in[5];
    const float* dWhh = (const float*)d_in[6];
    const float* dbih = (const float*)d_in[7];
    const float* dbhh = (const float*)d_in[8];
    const float* oW   = (const float*)d_in[9];
    const float* ob   = (const float*)d_in[10];
    float* out = (float*)d_out;

    // 4096 elements * 32 lanes = 131072 threads; 128/block -> 1024 blocks.
    // __launch_bounds__(128,7): 7 blocks/SM -> 1036 slots >= 1024, one wave.
    lstm_ae_kernel<<<1024, 128>>>(x, eWih, eWhh, ebih, ebhh,
                                  dWih, dWhh, dbih, dbhh, oW, ob, out);
}

// round 17
// speedup vs baseline: 1.9362x; 1.9362x over previous
#include <cuda_runtime.h>

// LSTM autoencoder, fully fused. B=4096, T=512, F=8, H=16.
// R8: 4 elements per warp. Half-warp = element slot (R6), PLUS two elements
// per thread (R4) with hand-interleaved phases so element B's FMA block
// executes under element A's MUFU latency. Shuffle-only h exchange, no smem,
// no volatile in the loops. Weights register-shared across both elements.

#define B_ 4096
#define T_ 512
#define F_ 8
#define H_ 16
#define XOFF (T_ * F_)

typedef unsigned long long u64;

__device__ __forceinline__ u64 pk2(float lo, float hi) {
    u64 r; asm("mov.b64 %0,{%1,%2};" : "=l"(r) : "f"(lo), "f"(hi)); return r;
}
__device__ __forceinline__ void fma2(u64& d, u64 a, u64 b) {
    asm("fma.rn.f32x2 %0,%1,%2,%0;" : "+l"(d) : "l"(a), "l"(b));
}
__device__ __forceinline__ float hadd2(u64 v) {
    float lo, hi; asm("mov.b64 {%0,%1},%2;" : "=f"(lo), "=f"(hi) : "l"(v));
    return lo + hi;
}
__device__ __forceinline__ float tanh_fast(float x) {
    float r; asm("tanh.approx.f32 %0,%1;" : "=f"(r) : "f"(x)); return r;
}
__device__ __forceinline__ void ldg2(u64& a, u64& b, const float* p) {
    asm("ld.global.nc.v2.u64 {%0,%1},[%2];" : "=l"(a), "=l"(b) : "l"(p));
}

__global__ __launch_bounds__(128, 2)
void lstm_ae_kernel(const float* __restrict__ x,
                    const float* __restrict__ eWih, const float* __restrict__ eWhh,
                    const float* __restrict__ ebih, const float* __restrict__ ebhh,
                    const float* __restrict__ dWih, const float* __restrict__ dWhh,
                    const float* __restrict__ dbih, const float* __restrict__ dbhh,
                    const float* __restrict__ oW,  const float* __restrict__ ob,
                    float* __restrict__ out)
{
    const int tid  = blockIdx.x * blockDim.x + threadIdx.x;
    const int warp = tid >> 5;
    const int l    = tid & 31;
    const int hw   = l >> 4;          // half-warp id
    const int u    = l & 15;          // hidden unit
    const unsigned FULL = 0xffffffffu;

    // elements handled by this thread: eA = 4w+hw, eB = 4w+2+hw
    const int eA = warp * 4 + hw;
    const int eB = eA + 2;

    // ---------- encoder weights (register resident, shared by A and B) ------
    // sigmoid gates (g!=2) pre-scaled by 0.5: sigmoid(z)=0.5*tanh(0.5z)+0.5
    u64 wh[4][8];  u64 wi[4][4];  float bias[4];
    #pragma unroll
    for (int g = 0; g < 4; ++g) {
        const int r = g * H_ + u;
        const float s = (g == 2) ? 1.0f : 0.5f;
        bias[g] = s * (ebih[r] + ebhh[r]);
        #pragma unroll
        for (int j = 0; j < 8; ++j)
            wh[g][j] = pk2(s * eWhh[r * H_ + 2 * j], s * eWhh[r * H_ + 2 * j + 1]);
        #pragma unroll
        for (int j = 0; j < 4; ++j)
            wi[g][j] = pk2(s * eWih[r * F_ + 2 * j], s * eWih[r * F_ + 2 * j + 1]);
    }

    const float* xrA = x + (size_t)eA * XOFF;
    const float* xrB = x + (size_t)eB * XOFF;

    float hA = 0.f, cA = 0.f, hB = 0.f, cB = 0.f;

    // ---------------- encoder recurrence ----------------
    for (int t = 0; t < T_; ++t) {
        // ===== phase 1: element A input proj + recurrent =====
        u64 a0 = pk2(bias[0], 0.f), a1 = pk2(bias[1], 0.f);
        u64 a2 = pk2(bias[2], 0.f), a3 = pk2(bias[3], 0.f);
        {
            u64 x0, x1, x2, x3;
            ldg2(x0, x1, xrA + t * F_);
            ldg2(x2, x3, xrA + t * F_ + 4);
            fma2(a0,x0,wi[0][0]); fma2(a1,x0,wi[1][0]); fma2(a2,x0,wi[2][0]); fma2(a3,x0,wi[3][0]);
            fma2(a0,x1,wi[0][1]); fma2(a1,x1,wi[1][1]); fma2(a2,x1,wi[2][1]); fma2(a3,x1,wi[3][1]);
            fma2(a0,x2,wi[0][2]); fma2(a1,x2,wi[1][2]); fma2(a2,x2,wi[2][2]); fma2(a3,x2,wi[3][2]);
            fma2(a0,x3,wi[0][3]); fma2(a1,x3,wi[1][3]); fma2(a2,x3,wi[2][3]); fma2(a3,x3,wi[3][3]);
        }
        #pragma unroll
        for (int k = 0; k < 8; ++k) {
            float hl = __shfl_sync(FULL, hA, 2 * k,     16);
            float hh = __shfl_sync(FULL, hA, 2 * k + 1, 16);
            u64 hp = pk2(hl, hh);
            fma2(a0, hp, wh[0][k]); fma2(a1, hp, wh[1][k]);
            fma2(a2, hp, wh[2][k]); fma2(a3, hp, wh[3][k]);
        }
        // ===== phase 2: launch A's MUFUs =====
        float tA0 = tanh_fast(hadd2(a0));
        float tA1 = tanh_fast(hadd2(a1));
        float tA2 = tanh_fast(hadd2(a2));
        float tA3 = tanh_fast(hadd2(a3));

        // ===== phase 3: element B input proj + recurrent (covers A's latency)
        u64 d0 = pk2(bias[0], 0.f), d1 = pk2(bias[1], 0.f);
        u64 d2 = pk2(bias[2], 0.f), d3 = pk2(bias[3], 0.f);
        {
            u64 y0, y1, y2, y3;
            ldg2(y0, y1, xrB + t * F_);
            ldg2(y2, y3, xrB + t * F_ + 4);
            fma2(d0,y0,wi[0][0]); fma2(d1,y0,wi[1][0]); fma2(d2,y0,wi[2][0]); fma2(d3,y0,wi[3][0]);
            fma2(d0,y1,wi[0][1]); fma2(d1,y1,wi[1][1]); fma2(d2,y1,wi[2][1]); fma2(d3,y1,wi[3][1]);
            fma2(d0,y2,wi[0][2]); fma2(d1,y2,wi[1][2]); fma2(d2,y2,wi[2][2]); fma2(d3,y2,wi[3][2]);
            fma2(d0,y3,wi[0][3]); fma2(d1,y3,wi[1][3]); fma2(d2,y3,wi[2][3]); fma2(d3,y3,wi[3][3]);
        }
        #pragma unroll
        for (int k = 0; k < 8; ++k) {
            float hl = __shfl_sync(FULL, hB, 2 * k,     16);
            float hh = __shfl_sync(FULL, hB, 2 * k + 1, 16);
            u64 hp = pk2(hl, hh);
            fma2(d0, hp, wh[0][k]); fma2(d1, hp, wh[1][k]);
            fma2(d2, hp, wh[2][k]); fma2(d3, hp, wh[3][k]);
        }
        // ===== phase 4: finish A =====
        {
            float ig = __fmaf_rn(0.5f, tA0, 0.5f);
            float fg = __fmaf_rn(0.5f, tA1, 0.5f);
            float og = __fmaf_rn(0.5f, tA3, 0.5f);
            cA = __fmaf_rn(fg, cA, ig * tA2);
            hA = og * tanh_fast(cA);
        }
        // ===== phase 5: B's MUFUs + finish B =====
        float tB0 = tanh_fast(hadd2(d0));
        float tB1 = tanh_fast(hadd2(d1));
        float tB2 = tanh_fast(hadd2(d2));
        float tB3 = tanh_fast(hadd2(d3));
        {
            float ig = __fmaf_rn(0.5f, tB0, 0.5f);
            float fg = __fmaf_rn(0.5f, tB1, 0.5f);
            float og = __fmaf_rn(0.5f, tB3, 0.5f);
            cB = __fmaf_rn(fg, cB, ig * tB2);
            hB = og * tanh_fast(cB);
        }
    }

    // ---------------- decoder setup ----------------
    float xgA[4], xgB[4];
    #pragma unroll
    for (int g = 0; g < 4; ++g) {
        const int r = g * H_ + u;
        float a = dbih[r] + dbhh[r], b2 = a;
        #pragma unroll
        for (int k = 0; k < H_; ++k) {
            float w  = __ldg(&dWih[r * H_ + k]);
            float ha = __shfl_sync(FULL, hA, k, 16);
            float hb = __shfl_sync(FULL, hB, k, 16);
            a  = __fmaf_rn(ha, w, a);
            b2 = __fmaf_rn(hb, w, b2);
        }
        const float s = (g == 2) ? 1.0f : 0.5f;
        xgA[g] = s * a;  xgB[g] = s * b2;
        #pragma unroll
        for (int j = 0; j < 8; ++j)
            wh[g][j] = pk2(s * dWhh[r * H_ + 2 * j], s * dWhh[r * H_ + 2 * j + 1]);
    }
    // output head: lane u&7 computes feature u&7; lanes u<8 store (reuse wi)
    const int fo = u & 7;
    #pragma unroll
    for (int j = 0; j < 4; ++j) {
        wi[0][j] = pk2(oW[fo * H_ + 2 * j],     oW[fo * H_ + 2 * j + 1]);
        wi[1][j] = pk2(oW[fo * H_ + 8 + 2 * j], oW[fo * H_ + 8 + 2 * j + 1]);
    }
    const float obv = __ldg(&ob[fo]);

    hA = cA = hB = cB = 0.f;
    float* outA = out + (size_t)eA * XOFF;
    float* outB = out + (size_t)eB * XOFF;

    // ---------------- decoder recurrence + fused output head ----------------
    for (int t = 0; t < T_; ++t) {
        // ===== A: recurrent + head =====
        u64 a0 = pk2(xgA[0], 0.f), a1 = pk2(xgA[1], 0.f);
        u64 a2 = pk2(xgA[2], 0.f), a3 = pk2(xgA[3], 0.f);
        u64 oa = pk2(obv, 0.f);
        #pragma unroll
        for (int k = 0; k < 8; ++k) {
            float hl = __shfl_sync(FULL, hA, 2 * k,     16);
            float hh = __shfl_sync(FULL, hA, 2 * k + 1, 16);
            u64 hp = pk2(hl, hh);
            fma2(a0, hp, wh[0][k]); fma2(a1, hp, wh[1][k]);
            fma2(a2, hp, wh[2][k]); fma2(a3, hp, wh[3][k]);
            fma2(oa, hp, (k < 4) ? wi[0][k] : wi[1][k - 4]);
        }
        float tA0 = tanh_fast(hadd2(a0));
        float tA1 = tanh_fast(hadd2(a1));
        float tA2 = tanh_fast(hadd2(a2));
        float tA3 = tanh_fast(hadd2(a3));
        if (t > 0 && u < 8) outA[(t - 1) * F_ + u] = hadd2(oa);

        // ===== B: recurrent + head (covers A's MUFU latency) =====
        u64 d0 = pk2(xgB[0], 0.f), d1 = pk2(xgB[1], 0.f);
        u64 d2 = pk2(xgB[2], 0.f), d3 = pk2(xgB[3], 0.f);
        u64 oc = pk2(obv, 0.f);
        #pragma unroll
        for (int k = 0; k < 8; ++k) {
            float hl = __shfl_sync(FULL, hB, 2 * k,     16);
            float hh = __shfl_sync(FULL, hB, 2 * k + 1, 16);
            u64 hp = pk2(hl, hh);
            fma2(d0, hp, wh[0][k]); fma2(d1, hp, wh[1][k]);
            fma2(d2, hp, wh[2][k]); fma2(d3, hp, wh[3][k]);
            fma2(oc, hp, (k < 4) ? wi[0][k] : wi[1][k - 4]);
        }
        // finish A
        {
            float ig = __fmaf_rn(0.5f, tA0, 0.5f);
            float fg = __fmaf_rn(0.5f, tA1, 0.5f);
            float og = __fmaf_rn(0.5f, tA3, 0.5f);
            cA = __fmaf_rn(fg, cA, ig * tA2);
            hA = og * tanh_fast(cA);
        }
        // B MUFUs + finish
        float tB0 = tanh_fast(hadd2(d0));
        float tB1 = tanh_fast(hadd2(d1));
        float tB2 = tanh_fast(hadd2(d2));
        float tB3 = tanh_fast(hadd2(d3));
        if (t > 0 && u < 8) outB[(t - 1) * F_ + u] = hadd2(oc);
        {
            float ig = __fmaf_rn(0.5f, tB0, 0.5f);
            float fg = __fmaf_rn(0.5f, tB1, 0.5f);
            float og = __fmaf_rn(0.5f, tB3, 0.5f);
            cB = __fmaf_rn(fg, cB, ig * tB2);
            hB = og * tanh_fast(cB);
        }
    }

    // epilogue: project decoded[T-1] for both elements
    {
        u64 oa = pk2(obv, 0.f), oc = pk2(obv, 0.f);
        #pragma unroll
        for (int k = 0; k < 8; ++k) {
            float al = __shfl_sync(FULL, hA, 2 * k,     16);
            float ah = __shfl_sync(FULL, hA, 2 * k + 1, 16);
            float bl = __shfl_sync(FULL, hB, 2 * k,     16);
            float bh = __shfl_sync(FULL, hB, 2 * k + 1, 16);
            u64 w = (k < 4) ? wi[0][k] : wi[1][k - 4];
            fma2(oa, pk2(al, ah), w);
            fma2(oc, pk2(bl, bh), w);
        }
        if (u < 8) {
            outA[(T_ - 1) * F_ + u] = hadd2(oa);
            outB[(T_ - 1) * F_ + u] = hadd2(oc);
        }
    }
}

extern "C" void kernel_launch(void* const* d_in, const int* in_sizes, int n_in,
                              void* d_out, int out_size)
{
    const float* x    = (const float*)d_in[0];
    const float* eWih = (const float*)d_in[1];
    const float* eWhh = (const float*)d_in[2];
    const float* ebih = (const float*)d_in[3];
    const float* ebhh = (const float*)d_in[4];
    const float* dWih = (const float*)d_in[5];
    const float* dWhh = (const float*)d_in[6];
    const float* dbih = (const float*)d_in[7];
    const float* dbhh = (const float*)d_in[8];
    const float* oW   = (const float*)d_in[9];
    const float* ob   = (const float*)d_in[10];
    float* out = (float*)d_out;

    // 4096 elements / 4 per warp = 1024 warps = 256 blocks of 128 threads
    lstm_ae_kernel<<<256, 128>>>(x, eWih, eWhh, ebih, ebhh,
                                 dWih, dWhh, dbih, dbhh, oW, ob, out);
}